// round 1
// baseline (speedup 1.0000x reference)
#include <cuda_runtime.h>
#include <math.h>

#define G   4          // batches per CTA
#define TS  32         // x_seq tile rows in SMEM
#define NHH 8
#define DD  512
#define SS  128
#define THREADS 256

// SMEM float counts
#define XS_F    (TS*DD)          // 16384
#define QTU_F   (G*NHH*DD)       // 16384  (qt, later reused as u)
#define QS_F    (G*DD)           // 2048
#define SC_F    (G*NHH*SS)       // 4096   (scores -> attn; also x_non staging)
#define QB_F    (G*NHH)          // 32
#define SMEM_F  (XS_F + QTU_F + QS_F + SC_F + QB_F)

__device__ __forceinline__ float warp_sum(float v) {
    v += __shfl_xor_sync(0xffffffffu, v, 16);
    v += __shfl_xor_sync(0xffffffffu, v, 8);
    v += __shfl_xor_sync(0xffffffffu, v, 4);
    v += __shfl_xor_sync(0xffffffffu, v, 2);
    v += __shfl_xor_sync(0xffffffffu, v, 1);
    return v;
}
__device__ __forceinline__ float warp_max(float v) {
    v = fmaxf(v, __shfl_xor_sync(0xffffffffu, v, 16));
    v = fmaxf(v, __shfl_xor_sync(0xffffffffu, v, 8));
    v = fmaxf(v, __shfl_xor_sync(0xffffffffu, v, 4));
    v = fmaxf(v, __shfl_xor_sync(0xffffffffu, v, 2));
    v = fmaxf(v, __shfl_xor_sync(0xffffffffu, v, 1));
    return v;
}

__global__ __launch_bounds__(THREADS, 1)
void mha_kernel(const float* __restrict__ x_non,
                const float* __restrict__ x_seq,
                const int*   __restrict__ mask,
                const float* __restrict__ Wq, const float* __restrict__ bq,
                const float* __restrict__ Wk, const float* __restrict__ bk,
                const float* __restrict__ Wv, const float* __restrict__ bv,
                float* __restrict__ out)
{
    extern __shared__ float smem[];
    float* xs  = smem;                 // [TS][512]
    float* qtu = xs + XS_F;            // [G][8][512]  qt then u
    float* qs  = qtu + QTU_F;          // [G][512]
    float* sc  = qs + QS_F;            // [G][8][128]  scores/attn (and x_non staging)
    float* qb  = sc + SC_F;            // [G][8]

    const int tid  = threadIdx.x;
    const int lane = tid & 31;
    const int w    = tid >> 5;         // warp id == head id
    const int b0   = blockIdx.x * G;

    // ---- stage x_non[b0..b0+G) into sc region ----
    for (int i = tid; i < G*DD; i += THREADS)
        sc[i] = x_non[(size_t)b0*DD + i];
    __syncthreads();

    // ---- phase 1: q[g][i] = Wq[i,:]·xn[g] + bq[i]  (warp w -> rows [w*64, w*64+64)) ----
    {
        float4 xr[G][4];
        #pragma unroll
        for (int g = 0; g < G; g++)
            #pragma unroll
            for (int m = 0; m < 4; m++)
                xr[g][m] = ((const float4*)sc)[g*128 + lane + 32*m];

        for (int r = 0; r < 64; r++) {
            const int i = w*64 + r;
            const float4* wrow = (const float4*)(Wq + (size_t)i*DD);
            float acc[G] = {0.f,0.f,0.f,0.f};
            #pragma unroll
            for (int m = 0; m < 4; m++) {
                float4 wv = wrow[lane + 32*m];
                #pragma unroll
                for (int g = 0; g < G; g++) {
                    acc[g] += wv.x*xr[g][m].x + wv.y*xr[g][m].y
                            + wv.z*xr[g][m].z + wv.w*xr[g][m].w;
                }
            }
            #pragma unroll
            for (int g = 0; g < G; g++) {
                float v = warp_sum(acc[g]);
                if (lane == 0) qs[g*DD + i] = v + bq[i];
            }
        }
    }
    __syncthreads();

    // ---- phase 2: qt[g][n][j] = sum_d Wk[n*64+d][j] * q[g][n*64+d] ; qb[g][n] = q·bk_n ----
    {
        for (int idx = tid; idx < NHH*128; idx += THREADS) {   // (n, j4)
            const int n  = idx >> 7;
            const int j4 = idx & 127;
            float4 acc[G];
            #pragma unroll
            for (int g = 0; g < G; g++) acc[g] = make_float4(0.f,0.f,0.f,0.f);
            const float4* wk4 = (const float4*)Wk + (size_t)(n*64)*128 + j4;
            #pragma unroll 4
            for (int d = 0; d < 64; d++) {
                float4 wv = wk4[(size_t)d*128];
                #pragma unroll
                for (int g = 0; g < G; g++) {
                    float qv = qs[g*DD + n*64 + d];
                    acc[g].x += wv.x*qv; acc[g].y += wv.y*qv;
                    acc[g].z += wv.z*qv; acc[g].w += wv.w*qv;
                }
            }
            #pragma unroll
            for (int g = 0; g < G; g++)
                ((float4*)qtu)[g*1024 + idx] = acc[g];
        }
        if (tid < G*NHH) {
            const int g = tid >> 3, n = tid & 7;
            float s = 0.f;
            for (int d = 0; d < 64; d++) s += qs[g*DD + n*64 + d] * bk[n*64 + d];
            qb[tid] = s;
        }
    }
    __syncthreads();

    // ---- per-batch attention ----
    for (int g = 0; g < G; g++) {
        const int b = b0 + g;
        const float4* xrow4g = (const float4*)(x_seq + (size_t)b * SS * DD);

        // hoist qt lane slice for head w
        float4 qtr[4];
        #pragma unroll
        for (int m = 0; m < 4; m++)
            qtr[m] = ((const float4*)qtu)[g*1024 + w*128 + lane + 32*m];

        // pass 1: scores (raw qk, bias added in softmax)
        for (int t = 0; t < 4; t++) {
            __syncthreads();
            for (int i = tid; i < TS*128; i += THREADS)
                ((float4*)xs)[i] = xrow4g[t*TS*128 + i];
            __syncthreads();
            for (int s = 0; s < TS; s++) {
                const float4* xr = (const float4*)(xs + s*DD);
                float a = 0.f;
                #pragma unroll
                for (int m = 0; m < 4; m++) {
                    float4 xv = xr[lane + 32*m];
                    a += xv.x*qtr[m].x + xv.y*qtr[m].y + xv.z*qtr[m].z + xv.w*qtr[m].w;
                }
                a = warp_sum(a);
                if (lane == 0) sc[g*1024 + w*SS + t*TS + s] = a;
            }
        }

        // softmax (warp-local: head w)
        {
            const int* mrow = mask + ((size_t)b*NHH + w)*SS;
            const float qbb = qb[g*NHH + w];
            float l[4];
            #pragma unroll
            for (int k = 0; k < 4; k++) {
                const int s = lane + 32*k;
                float raw = sc[g*1024 + w*SS + s] + qbb;
                l[k] = (mrow[s] != 0) ? floorf(raw * 0.125f) : -1e30f;
            }
            float mx = fmaxf(fmaxf(l[0],l[1]), fmaxf(l[2],l[3]));
            mx = warp_max(mx);
            float e[4]; float ssum = 0.f;
            #pragma unroll
            for (int k = 0; k < 4; k++) { e[k] = expf(l[k] - mx); ssum += e[k]; }
            ssum = warp_sum(ssum);
            const float inv = 1.0f / ssum;
            #pragma unroll
            for (int k = 0; k < 4; k++)
                sc[g*1024 + w*SS + lane + 32*k] = e[k] * inv;
        }

        // pass 2: u = sum_s attn[s] * x_seq[s]  (reverse tiles; t=3 is still resident)
        {
            float4 ua[4];
            #pragma unroll
            for (int m = 0; m < 4; m++) ua[m] = make_float4(0.f,0.f,0.f,0.f);
            for (int t = 3; t >= 0; t--) {
                if (t != 3) {
                    __syncthreads();
                    for (int i = tid; i < TS*128; i += THREADS)
                        ((float4*)xs)[i] = xrow4g[t*TS*128 + i];
                    __syncthreads();
                }
                for (int s = 0; s < TS; s++) {
                    const float wgt = sc[g*1024 + w*SS + t*TS + s];
                    const float4* xr = (const float4*)(xs + s*DD);
                    #pragma unroll
                    for (int m = 0; m < 4; m++) {
                        float4 xv = xr[lane + 32*m];
                        ua[m].x += wgt*xv.x; ua[m].y += wgt*xv.y;
                        ua[m].z += wgt*xv.z; ua[m].w += wgt*xv.w;
                    }
                }
            }
            #pragma unroll
            for (int m = 0; m < 4; m++)
                ((float4*)qtu)[g*1024 + w*128 + lane + 32*m] = ua[m];  // qt[g] dead -> u[g]
        }
    }
    __syncthreads();

    // ---- phase z: out[b_g][i] = Wv[i,:]·u[g][n] + bv[i]  (warp w -> head w rows) ----
    {
        float4 ur[G][4];
        #pragma unroll
        for (int g = 0; g < G; g++)
            #pragma unroll
            for (int m = 0; m < 4; m++)
                ur[g][m] = ((const float4*)qtu)[g*1024 + w*128 + lane + 32*m];

        for (int r = 0; r < 64; r++) {
            const int i = w*64 + r;
            const float4* wrow = (const float4*)(Wv + (size_t)i*DD);
            float acc[G] = {0.f,0.f,0.f,0.f};
            #pragma unroll
            for (int m = 0; m < 4; m++) {
                float4 wv = wrow[lane + 32*m];
                #pragma unroll
                for (int g = 0; g < G; g++) {
                    acc[g] += wv.x*ur[g][m].x + wv.y*ur[g][m].y
                            + wv.z*ur[g][m].z + wv.w*ur[g][m].w;
                }
            }
            const float bvi = bv[i];
            #pragma unroll
            for (int g = 0; g < G; g++) {
                float v = warp_sum(acc[g]);
                if (lane == 0) out[(size_t)(b0+g)*DD + i] = v + bvi;
            }
        }
    }
}

extern "C" void kernel_launch(void* const* d_in, const int* in_sizes, int n_in,
                              void* d_out, int out_size)
{
    const float* x_non = (const float*)d_in[0];
    const float* x_seq = (const float*)d_in[1];
    const int*   mask  = (const int*)  d_in[2];
    const float* Wq    = (const float*)d_in[3];
    const float* bq    = (const float*)d_in[4];
    const float* Wk    = (const float*)d_in[5];
    const float* bk    = (const float*)d_in[6];
    const float* Wv    = (const float*)d_in[7];
    const float* bv    = (const float*)d_in[8];
    float* out = (float*)d_out;

    const int smem_bytes = SMEM_F * (int)sizeof(float);   // ~152 KB
    cudaFuncSetAttribute(mha_kernel, cudaFuncAttributeMaxDynamicSharedMemorySize, smem_bytes);
    mha_kernel<<<1024/G, THREADS, smem_bytes>>>(x_non, x_seq, mask,
                                                Wq, bq, Wk, bk, Wv, bv, out);
}

// round 2
// speedup vs baseline: 2.3639x; 2.3639x over previous
#include <cuda_runtime.h>
#include <math.h>

#define G   4          // batches per CTA
#define TS  32         // x_seq tile rows in SMEM
#define NHH 8
#define DD  512
#define SS  128
#define THREADS 512    // 16 warps

// SMEM float counts
#define XS_F    (TS*DD)          // 16384 (also reused as pass-2 partial-u scratch)
#define QTU_F   (G*NHH*DD)       // 16384  (qt, later reused as u)
#define QS_F    (G*DD)           // 2048
#define SC_F    (G*NHH*SS)       // 4096   (scores -> attn; also x_non staging)
#define QB_F    (G*NHH)          // 32
#define SMEM_F  (XS_F + QTU_F + QS_F + SC_F + QB_F)

__device__ __forceinline__ float warp_sum(float v) {
    v += __shfl_xor_sync(0xffffffffu, v, 16);
    v += __shfl_xor_sync(0xffffffffu, v, 8);
    v += __shfl_xor_sync(0xffffffffu, v, 4);
    v += __shfl_xor_sync(0xffffffffu, v, 2);
    v += __shfl_xor_sync(0xffffffffu, v, 1);
    return v;
}
__device__ __forceinline__ float warp_max(float v) {
    v = fmaxf(v, __shfl_xor_sync(0xffffffffu, v, 16));
    v = fmaxf(v, __shfl_xor_sync(0xffffffffu, v, 8));
    v = fmaxf(v, __shfl_xor_sync(0xffffffffu, v, 4));
    v = fmaxf(v, __shfl_xor_sync(0xffffffffu, v, 2));
    v = fmaxf(v, __shfl_xor_sync(0xffffffffu, v, 1));
    return v;
}

__global__ __launch_bounds__(THREADS, 1)
void mha_kernel(const float* __restrict__ x_non,
                const float* __restrict__ x_seq,
                const int*   __restrict__ mask,
                const float* __restrict__ Wq, const float* __restrict__ bq,
                const float* __restrict__ Wk, const float* __restrict__ bk,
                const float* __restrict__ Wv, const float* __restrict__ bv,
                float* __restrict__ out)
{
    extern __shared__ float smem[];
    float* xs  = smem;                 // [TS][512] tile; later [4][8][512] partial-u scratch
    float* qtu = xs + XS_F;            // [G][8][512]  qt then u
    float* qs  = qtu + QTU_F;          // [G][512]
    float* sc  = qs + QS_F;            // [G][8][128]  scores/attn (and x_non staging)
    float* qb  = sc + SC_F;            // [G][8]

    float4* xs4  = (float4*)xs;
    float4* qtu4 = (float4*)qtu;

    const int tid  = threadIdx.x;
    const int lane = tid & 31;
    const int w    = tid >> 5;         // 0..15
    const int b0   = blockIdx.x * G;

    // pass decomposition: head pair + s-quarter
    const int hg = w >> 2;             // 0..3 -> heads {2hg, 2hg+1}
    const int sq = w & 3;              // 0..3 -> tile rows [sq*8, sq*8+8)
    const int h0 = hg * 2;

    // ---- stage x_non[b0..b0+G) into sc region ----
    for (int i = tid; i < G*DD; i += THREADS)
        sc[i] = x_non[(size_t)b0*DD + i];
    __syncthreads();

    // ---- phase 1: q[g][i] = Wq[i,:]·xn[g] + bq[i]  (warp w -> rows [w*32, w*32+32)) ----
    {
        float4 xr[G][4];
        #pragma unroll
        for (int g = 0; g < G; g++)
            #pragma unroll
            for (int m = 0; m < 4; m++)
                xr[g][m] = ((const float4*)sc)[g*128 + lane + 32*m];

        for (int r = 0; r < 32; r++) {
            const int i = w*32 + r;
            const float4* wrow = (const float4*)(Wq + (size_t)i*DD);
            float acc[G] = {0.f,0.f,0.f,0.f};
            #pragma unroll
            for (int m = 0; m < 4; m++) {
                float4 wv = wrow[lane + 32*m];
                #pragma unroll
                for (int g = 0; g < G; g++) {
                    acc[g] += wv.x*xr[g][m].x + wv.y*xr[g][m].y
                            + wv.z*xr[g][m].z + wv.w*xr[g][m].w;
                }
            }
            #pragma unroll
            for (int g = 0; g < G; g++) {
                float v = warp_sum(acc[g]);
                if (lane == 0) qs[g*DD + i] = v + bq[i];
            }
        }
    }
    __syncthreads();

    // ---- phase 2: qt[g][n][j] = sum_d Wk[n*64+d][j] * q[g][n*64+d] ; qb[g][n] = q·bk_n ----
    {
        for (int idx = tid; idx < NHH*128; idx += THREADS) {   // (n, j4)
            const int n  = idx >> 7;
            const int j4 = idx & 127;
            float4 acc[G];
            #pragma unroll
            for (int g = 0; g < G; g++) acc[g] = make_float4(0.f,0.f,0.f,0.f);
            const float4* wk4 = (const float4*)Wk + (size_t)(n*64)*128 + j4;
            #pragma unroll 4
            for (int d = 0; d < 64; d++) {
                float4 wv = wk4[(size_t)d*128];
                #pragma unroll
                for (int g = 0; g < G; g++) {
                    float qv = qs[g*DD + n*64 + d];
                    acc[g].x += wv.x*qv; acc[g].y += wv.y*qv;
                    acc[g].z += wv.z*qv; acc[g].w += wv.w*qv;
                }
            }
            #pragma unroll
            for (int g = 0; g < G; g++)
                qtu4[g*1024 + idx] = acc[g];
        }
        if (tid < G*NHH) {
            const int g = tid >> 3, n = tid & 7;
            float s = 0.f;
            for (int d = 0; d < 64; d++) s += qs[g*DD + n*64 + d] * bk[n*64 + d];
            qb[tid] = s;
        }
    }
    __syncthreads();

    // ---- per-batch attention ----
    for (int g = 0; g < G; g++) {
        const int b = b0 + g;
        const float4* xrow4g = (const float4*)(x_seq + (size_t)b * SS * DD);

        // hoist qt lane slices for the warp's 2 heads
        float4 qtr0[4], qtr1[4];
        #pragma unroll
        for (int m = 0; m < 4; m++) {
            qtr0[m] = qtu4[g*1024 + (h0+0)*128 + lane + 32*m];
            qtr1[m] = qtu4[g*1024 + (h0+1)*128 + lane + 32*m];
        }

        // pass 1: raw scores (bias added in softmax)
        for (int t = 0; t < 4; t++) {
            __syncthreads();
            for (int i = tid; i < TS*128; i += THREADS)
                xs4[i] = xrow4g[t*TS*128 + i];
            __syncthreads();
            #pragma unroll 2
            for (int sr = 0; sr < 8; sr++) {
                const int srow = sq*8 + sr;
                const float4* xr = (const float4*)(xs + srow*DD);
                float a0 = 0.f, a1 = 0.f;
                #pragma unroll
                for (int m = 0; m < 4; m++) {
                    float4 xv = xr[lane + 32*m];
                    a0 += xv.x*qtr0[m].x + xv.y*qtr0[m].y + xv.z*qtr0[m].z + xv.w*qtr0[m].w;
                    a1 += xv.x*qtr1[m].x + xv.y*qtr1[m].y + xv.z*qtr1[m].z + xv.w*qtr1[m].w;
                }
                a0 = warp_sum(a0);
                a1 = warp_sum(a1);
                if (lane == 0) {
                    sc[g*1024 + (h0+0)*SS + t*TS + srow] = a0;
                    sc[g*1024 + (h0+1)*SS + t*TS + srow] = a1;
                }
            }
        }
        __syncthreads();

        // softmax (warps 0..7, warp w -> head w)
        if (w < NHH) {
            const int* mrow = mask + ((size_t)b*NHH + w)*SS;
            const float qbb = qb[g*NHH + w];
            float l[4];
            #pragma unroll
            for (int k = 0; k < 4; k++) {
                const int s = lane + 32*k;
                float raw = sc[g*1024 + w*SS + s] + qbb;
                l[k] = (mrow[s] != 0) ? floorf(raw * 0.125f) : -1e30f;
            }
            float mx = fmaxf(fmaxf(l[0],l[1]), fmaxf(l[2],l[3]));
            mx = warp_max(mx);
            float e[4]; float ssum = 0.f;
            #pragma unroll
            for (int k = 0; k < 4; k++) { e[k] = expf(l[k] - mx); ssum += e[k]; }
            ssum = warp_sum(ssum);
            const float inv = 1.0f / ssum;
            #pragma unroll
            for (int k = 0; k < 4; k++)
                sc[g*1024 + w*SS + lane + 32*k] = e[k] * inv;
        }
        __syncthreads();

        // pass 2: partial u over this warp's s-quarter, 2 heads (t=3 tile still resident)
        {
            float4 ua0[4], ua1[4];
            #pragma unroll
            for (int m = 0; m < 4; m++) {
                ua0[m] = make_float4(0.f,0.f,0.f,0.f);
                ua1[m] = make_float4(0.f,0.f,0.f,0.f);
            }
            for (int t = 3; t >= 0; t--) {
                if (t != 3) {
                    __syncthreads();
                    for (int i = tid; i < TS*128; i += THREADS)
                        xs4[i] = xrow4g[t*TS*128 + i];
                    __syncthreads();
                }
                #pragma unroll 2
                for (int sr = 0; sr < 8; sr++) {
                    const int srow = sq*8 + sr;
                    const float w0 = sc[g*1024 + (h0+0)*SS + t*TS + srow];
                    const float w1 = sc[g*1024 + (h0+1)*SS + t*TS + srow];
                    const float4* xr = (const float4*)(xs + srow*DD);
                    #pragma unroll
                    for (int m = 0; m < 4; m++) {
                        float4 xv = xr[lane + 32*m];
                        ua0[m].x += w0*xv.x; ua0[m].y += w0*xv.y;
                        ua0[m].z += w0*xv.z; ua0[m].w += w0*xv.w;
                        ua1[m].x += w1*xv.x; ua1[m].y += w1*xv.y;
                        ua1[m].z += w1*xv.z; ua1[m].w += w1*xv.w;
                    }
                }
            }
            // dump partials into xs scratch: [sq][head][512]
            __syncthreads();
            #pragma unroll
            for (int m = 0; m < 4; m++) {
                xs4[(sq*8 + h0+0)*128 + lane + 32*m] = ua0[m];
                xs4[(sq*8 + h0+1)*128 + lane + 32*m] = ua1[m];
            }
            __syncthreads();
            // reduce across s-quarters -> u in qtu[g]
            for (int idx = tid; idx < NHH*128; idx += THREADS) {
                float4 s0 = xs4[(0*8)*128 + idx];
                float4 s1 = xs4[(1*8)*128 + idx];
                float4 s2 = xs4[(2*8)*128 + idx];
                float4 s3 = xs4[(3*8)*128 + idx];
                float4 r;
                r.x = (s0.x + s1.x) + (s2.x + s3.x);
                r.y = (s0.y + s1.y) + (s2.y + s3.y);
                r.z = (s0.z + s1.z) + (s2.z + s3.z);
                r.w = (s0.w + s1.w) + (s2.w + s3.w);
                qtu4[g*1024 + idx] = r;
            }
        }
    }
    __syncthreads();

    // ---- phase z: out[b_g][i] = Wv[i,:]·u[g][head(i)] + bv[i] (warp w -> rows [w*32,w*32+32)) ----
    {
        const int zn = w >> 1;   // head for this warp's rows
        float4 ur[G][4];
        #pragma unroll
        for (int g = 0; g < G; g++)
            #pragma unroll
            for (int m = 0; m < 4; m++)
                ur[g][m] = qtu4[g*1024 + zn*128 + lane + 32*m];

        for (int r = 0; r < 32; r++) {
            const int i = w*32 + r;
            const float4* wrow = (const float4*)(Wv + (size_t)i*DD);
            float acc[G] = {0.f,0.f,0.f,0.f};
            #pragma unroll
            for (int m = 0; m < 4; m++) {
                float4 wv = wrow[lane + 32*m];
                #pragma unroll
                for (int g = 0; g < G; g++) {
                    acc[g] += wv.x*ur[g][m].x + wv.y*ur[g][m].y
                            + wv.z*ur[g][m].z + wv.w*ur[g][m].w;
                }
            }
            const float bvi = bv[i];
            #pragma unroll
            for (int g = 0; g < G; g++) {
                float v = warp_sum(acc[g]);
                if (lane == 0) out[(size_t)(b0+g)*DD + i] = v + bvi;
            }
        }
    }
}

extern "C" void kernel_launch(void* const* d_in, const int* in_sizes, int n_in,
                              void* d_out, int out_size)
{
    const float* x_non = (const float*)d_in[0];
    const float* x_seq = (const float*)d_in[1];
    const int*   mask  = (const int*)  d_in[2];
    const float* Wq    = (const float*)d_in[3];
    const float* bq    = (const float*)d_in[4];
    const float* Wk    = (const float*)d_in[5];
    const float* bk    = (const float*)d_in[6];
    const float* Wv    = (const float*)d_in[7];
    const float* bv    = (const float*)d_in[8];
    float* out = (float*)d_out;

    const int smem_bytes = SMEM_F * (int)sizeof(float);   // ~152 KB
    cudaFuncSetAttribute(mha_kernel, cudaFuncAttributeMaxDynamicSharedMemorySize, smem_bytes);
    mha_kernel<<<1024/G, THREADS, smem_bytes>>>(x_non, x_seq, mask,
                                                Wq, bq, Wk, bk, Wv, bv, out);
}

// round 3
// speedup vs baseline: 2.9524x; 1.2489x over previous
#include <cuda_runtime.h>
#include <math.h>

#define G   4          // batches per CTA
#define TS  16         // x_seq tile rows per buffer
#define NT  8          // tiles per batch (128/TS)
#define NHH 8
#define DD  512
#define SS  128
#define THREADS 512    // 16 warps

// SMEM float counts
#define BUF_F   (TS*DD)              // 8192 per buffer
#define XS_F    (2*BUF_F)            // 16384 (double buffer; also pass-2 partial scratch [4][8][512])
#define QTU_F   (G*NHH*DD)           // 16384  (qt, later reused as u)
#define QS_F    (G*DD)               // 2048
#define SC_F    (G*NHH*SS)           // 4096   (scores -> attn; also x_non staging)
#define QB_F    (G*NHH)              // 32
#define SMEM_F  (XS_F + QTU_F + QS_F + SC_F + QB_F)

__device__ __forceinline__ float warp_sum(float v) {
    v += __shfl_xor_sync(0xffffffffu, v, 16);
    v += __shfl_xor_sync(0xffffffffu, v, 8);
    v += __shfl_xor_sync(0xffffffffu, v, 4);
    v += __shfl_xor_sync(0xffffffffu, v, 2);
    v += __shfl_xor_sync(0xffffffffu, v, 1);
    return v;
}
__device__ __forceinline__ float warp_max(float v) {
    v = fmaxf(v, __shfl_xor_sync(0xffffffffu, v, 16));
    v = fmaxf(v, __shfl_xor_sync(0xffffffffu, v, 8));
    v = fmaxf(v, __shfl_xor_sync(0xffffffffu, v, 4));
    v = fmaxf(v, __shfl_xor_sync(0xffffffffu, v, 2));
    v = fmaxf(v, __shfl_xor_sync(0xffffffffu, v, 1));
    return v;
}

__device__ __forceinline__ void cp16(float4* dst_smem, const float4* src) {
    unsigned int d = (unsigned int)__cvta_generic_to_shared(dst_smem);
    asm volatile("cp.async.cg.shared.global [%0], [%1], 16;\n" :: "r"(d), "l"(src));
}
__device__ __forceinline__ void cp_commit() {
    asm volatile("cp.async.commit_group;\n" ::: "memory");
}
template <int N>
__device__ __forceinline__ void cp_wait() {
    asm volatile("cp.async.wait_group %0;\n" :: "n"(N) : "memory");
}

__global__ __launch_bounds__(THREADS, 1)
void mha_kernel(const float* __restrict__ x_non,
                const float* __restrict__ x_seq,
                const int*   __restrict__ mask,
                const float* __restrict__ Wq, const float* __restrict__ bq,
                const float* __restrict__ Wk, const float* __restrict__ bk,
                const float* __restrict__ Wv, const float* __restrict__ bv,
                float* __restrict__ out)
{
    extern __shared__ float smem[];
    float* xs  = smem;                 // 2 x [TS][512]; later [4][8][512] partial-u scratch
    float* qtu = xs + XS_F;            // [G][8][512]  qt then u
    float* qs  = qtu + QTU_F;          // [G][512]
    float* sc  = qs + QS_F;            // [G][8][128]  scores/attn (and x_non staging)
    float* qb  = sc + SC_F;            // [G][8]

    float4* xs4  = (float4*)xs;
    float4* qtu4 = (float4*)qtu;

    const int tid  = threadIdx.x;
    const int lane = tid & 31;
    const int w    = tid >> 5;         // 0..15
    const int b0   = blockIdx.x * G;

    // pass-1 mapping: head quad + s-slice of 2 rows
    const int hq  = w >> 3;            // 0..1 -> heads hq*4 .. hq*4+3
    const int sl1 = w & 7;             // rows [sl1*2, sl1*2+2) of tile
    // pass-2 mapping: head pair + s-slice of 4 rows
    const int hp  = w >> 2;            // 0..3 -> heads hp*2, hp*2+1
    const int sl2 = w & 3;             // rows [sl2*4, sl2*4+4) of tile

    // ---- stage x_non[b0..b0+G) into sc region ----
    for (int i = tid; i < G*DD; i += THREADS)
        sc[i] = x_non[(size_t)b0*DD + i];
    __syncthreads();

    // ---- phase 1: q[g][i] = Wq[i,:]·xn[g] + bq[i]  (warp w -> rows [w*32, w*32+32)) ----
    {
        float4 xr[G][4];
        #pragma unroll
        for (int g = 0; g < G; g++)
            #pragma unroll
            for (int m = 0; m < 4; m++)
                xr[g][m] = ((const float4*)sc)[g*128 + lane + 32*m];

        for (int r = 0; r < 32; r++) {
            const int i = w*32 + r;
            const float4* wrow = (const float4*)(Wq + (size_t)i*DD);
            float acc[G] = {0.f,0.f,0.f,0.f};
            #pragma unroll
            for (int m = 0; m < 4; m++) {
                float4 wv = wrow[lane + 32*m];
                #pragma unroll
                for (int g = 0; g < G; g++) {
                    acc[g] += wv.x*xr[g][m].x + wv.y*xr[g][m].y
                            + wv.z*xr[g][m].z + wv.w*xr[g][m].w;
                }
            }
            #pragma unroll
            for (int g = 0; g < G; g++) {
                float v = warp_sum(acc[g]);
                if (lane == 0) qs[g*DD + i] = v + bq[i];
            }
        }
    }
    __syncthreads();

    // ---- phase 2: qt[g][n][j] = sum_d Wk[n*64+d][j] * q[g][n*64+d] ; qb[g][n] = q·bk_n ----
    {
        for (int idx = tid; idx < NHH*128; idx += THREADS) {   // (n, j4)
            const int n  = idx >> 7;
            const int j4 = idx & 127;
            float4 acc[G];
            #pragma unroll
            for (int g = 0; g < G; g++) acc[g] = make_float4(0.f,0.f,0.f,0.f);
            const float4* wk4 = (const float4*)Wk + (size_t)(n*64)*128 + j4;
            #pragma unroll 4
            for (int d = 0; d < 64; d++) {
                float4 wv = wk4[(size_t)d*128];
                #pragma unroll
                for (int g = 0; g < G; g++) {
                    float qv = qs[g*DD + n*64 + d];
                    acc[g].x += wv.x*qv; acc[g].y += wv.y*qv;
                    acc[g].z += wv.z*qv; acc[g].w += wv.w*qv;
                }
            }
            #pragma unroll
            for (int g = 0; g < G; g++)
                qtu4[g*1024 + idx] = acc[g];
        }
        if (tid < G*NHH) {
            const int g = tid >> 3, n = tid & 7;
            float s = 0.f;
            for (int d = 0; d < 64; d++) s += qs[g*DD + n*64 + d] * bk[n*64 + d];
            qb[tid] = s;
        }
    }
    __syncthreads();

    // ---- per-batch attention ----
    for (int g = 0; g < G; g++) {
        const int b = b0 + g;
        const float4* xb4 = (const float4*)(x_seq + (size_t)b * SS * DD);  // 2048 float4 per tile

        // hoist qt lane slices for this warp's 4 heads (pass-1)
        float4 qtr[4][4];
        #pragma unroll
        for (int h = 0; h < 4; h++)
            #pragma unroll
            for (int m = 0; m < 4; m++)
                qtr[h][m] = qtu4[g*1024 + (hq*4+h)*128 + lane + 32*m];

        // prime tile 0
        {
            float4* dst = xs4;   // buf0
            const float4* src = xb4;
            #pragma unroll
            for (int i = 0; i < 4; i++) cp16(&dst[tid + 512*i], &src[tid + 512*i]);
            cp_commit();
        }

        // ---- pass 1: raw scores (bias added in softmax) ----
        for (int t = 0; t < NT; t++) {
            __syncthreads();   // everyone done with buf[(t+1)&1]'s old contents
            if (t + 1 < NT) {
                float4* dst = xs4 + ((t+1)&1)*2048;
                const float4* src = xb4 + (size_t)(t+1)*2048;
                #pragma unroll
                for (int i = 0; i < 4; i++) cp16(&dst[tid + 512*i], &src[tid + 512*i]);
                cp_commit();
                cp_wait<1>();
            } else {
                cp_wait<0>();
            }
            __syncthreads();   // tile t visible to all

            const float* buf = xs + (t&1)*BUF_F;
            #pragma unroll 2
            for (int r = 0; r < 2; r++) {
                const int srow = sl1*2 + r;
                const float4* xr = (const float4*)(buf + srow*DD);
                float a0=0.f, a1=0.f, a2=0.f, a3=0.f;
                #pragma unroll
                for (int m = 0; m < 4; m++) {
                    float4 xv = xr[lane + 32*m];
                    a0 += xv.x*qtr[0][m].x + xv.y*qtr[0][m].y + xv.z*qtr[0][m].z + xv.w*qtr[0][m].w;
                    a1 += xv.x*qtr[1][m].x + xv.y*qtr[1][m].y + xv.z*qtr[1][m].z + xv.w*qtr[1][m].w;
                    a2 += xv.x*qtr[2][m].x + xv.y*qtr[2][m].y + xv.z*qtr[2][m].z + xv.w*qtr[2][m].w;
                    a3 += xv.x*qtr[3][m].x + xv.y*qtr[3][m].y + xv.z*qtr[3][m].z + xv.w*qtr[3][m].w;
                }
                a0 = warp_sum(a0); a1 = warp_sum(a1);
                a2 = warp_sum(a2); a3 = warp_sum(a3);
                if (lane == 0) {
                    const int s = t*TS + srow;
                    sc[g*1024 + (hq*4+0)*SS + s] = a0;
                    sc[g*1024 + (hq*4+1)*SS + s] = a1;
                    sc[g*1024 + (hq*4+2)*SS + s] = a2;
                    sc[g*1024 + (hq*4+3)*SS + s] = a3;
                }
            }
        }
        __syncthreads();

        // ---- softmax (warps 0..7, warp w -> head w) ----
        if (w < NHH) {
            const int* mrow = mask + ((size_t)b*NHH + w)*SS;
            const float qbb = qb[g*NHH + w];
            float l[4];
            #pragma unroll
            for (int k = 0; k < 4; k++) {
                const int s = lane + 32*k;
                float raw = sc[g*1024 + w*SS + s] + qbb;
                l[k] = (mrow[s] != 0) ? floorf(raw * 0.125f) : -1e30f;
            }
            float mx = fmaxf(fmaxf(l[0],l[1]), fmaxf(l[2],l[3]));
            mx = warp_max(mx);
            float e[4]; float ssum = 0.f;
            #pragma unroll
            for (int k = 0; k < 4; k++) { e[k] = expf(l[k] - mx); ssum += e[k]; }
            ssum = warp_sum(ssum);
            const float inv = 1.0f / ssum;
            #pragma unroll
            for (int k = 0; k < 4; k++)
                sc[g*1024 + w*SS + lane + 32*k] = e[k] * inv;
        }
        __syncthreads();

        // ---- pass 2 (reverse tiles; 7 and 6 still resident from pass 1) ----
        {
            const int h0 = hp*2;
            float4 ua0[4], ua1[4];
            #pragma unroll
            for (int m = 0; m < 4; m++) {
                ua0[m] = make_float4(0.f,0.f,0.f,0.f);
                ua1[m] = make_float4(0.f,0.f,0.f,0.f);
            }
            for (int t = NT-1; t >= 0; t--) {
                if (t <= NT-3) {              // prefetched tile: wait for it
                    if (t > 0) cp_wait<1>(); else cp_wait<0>();
                    __syncthreads();
                }
                const float* buf = xs + (t&1)*BUF_F;
                #pragma unroll 2
                for (int r = 0; r < 4; r++) {
                    const int srow = sl2*4 + r;
                    const float w0 = sc[g*1024 + (h0+0)*SS + t*TS + srow];
                    const float w1 = sc[g*1024 + (h0+1)*SS + t*TS + srow];
                    const float4* xr = (const float4*)(buf + srow*DD);
                    #pragma unroll
                    for (int m = 0; m < 4; m++) {
                        float4 xv = xr[lane + 32*m];
                        ua0[m].x += w0*xv.x; ua0[m].y += w0*xv.y;
                        ua0[m].z += w0*xv.z; ua0[m].w += w0*xv.w;
                        ua1[m].x += w1*xv.x; ua1[m].y += w1*xv.y;
                        ua1[m].z += w1*xv.z; ua1[m].w += w1*xv.w;
                    }
                }
                __syncthreads();    // done reading buf[t&1]
                if (t - 2 >= 0) {   // prefetch tile t-2 into the buffer just freed
                    float4* dst = xs4 + (t&1)*2048;
                    const float4* src = xb4 + (size_t)(t-2)*2048;
                    #pragma unroll
                    for (int i = 0; i < 4; i++) cp16(&dst[tid + 512*i], &src[tid + 512*i]);
                    cp_commit();
                }
            }

            // dump partials into xs scratch: [sl2][head][512]
            #pragma unroll
            for (int m = 0; m < 4; m++) {
                xs4[(sl2*8 + h0+0)*128 + lane + 32*m] = ua0[m];
                xs4[(sl2*8 + h0+1)*128 + lane + 32*m] = ua1[m];
            }
            __syncthreads();
            // reduce across the 4 s-slices -> u in qtu[g]
            for (int idx = tid; idx < NHH*128; idx += THREADS) {
                float4 s0 = xs4[0*1024 + idx];
                float4 s1 = xs4[1*1024 + idx];
                float4 s2 = xs4[2*1024 + idx];
                float4 s3 = xs4[3*1024 + idx];
                float4 r;
                r.x = (s0.x + s1.x) + (s2.x + s3.x);
                r.y = (s0.y + s1.y) + (s2.y + s3.y);
                r.z = (s0.z + s1.z) + (s2.z + s3.z);
                r.w = (s0.w + s1.w) + (s2.w + s3.w);
                qtu4[g*1024 + idx] = r;
            }
            __syncthreads();   // scratch consumed before next batch's priming
        }
    }

    // ---- phase z: out[b_g][i] = Wv[i,:]·u[g][head(i)] + bv[i] (warp w -> rows [w*32,w*32+32)) ----
    {
        const int zn = w >> 1;   // head for this warp's rows
        float4 ur[G][4];
        #pragma unroll
        for (int g = 0; g < G; g++)
            #pragma unroll
            for (int m = 0; m < 4; m++)
                ur[g][m] = qtu4[g*1024 + zn*128 + lane + 32*m];

        for (int r = 0; r < 32; r++) {
            const int i = w*32 + r;
            const float4* wrow = (const float4*)(Wv + (size_t)i*DD);
            float acc[G] = {0.f,0.f,0.f,0.f};
            #pragma unroll
            for (int m = 0; m < 4; m++) {
                float4 wv = wrow[lane + 32*m];
                #pragma unroll
                for (int g = 0; g < G; g++) {
                    acc[g] += wv.x*ur[g][m].x + wv.y*ur[g][m].y
                            + wv.z*ur[g][m].z + wv.w*ur[g][m].w;
                }
            }
            const float bvi = bv[i];
            #pragma unroll
            for (int g = 0; g < G; g++) {
                float v = warp_sum(acc[g]);
                if (lane == 0) out[(size_t)(b0+g)*DD + i] = v + bvi;
            }
        }
    }
}

extern "C" void kernel_launch(void* const* d_in, const int* in_sizes, int n_in,
                              void* d_out, int out_size)
{
    const float* x_non = (const float*)d_in[0];
    const float* x_seq = (const float*)d_in[1];
    const int*   mask  = (const int*)  d_in[2];
    const float* Wq    = (const float*)d_in[3];
    const float* bq    = (const float*)d_in[4];
    const float* Wk    = (const float*)d_in[5];
    const float* bk    = (const float*)d_in[6];
    const float* Wv    = (const float*)d_in[7];
    const float* bv    = (const float*)d_in[8];
    float* out = (float*)d_out;

    const int smem_bytes = SMEM_F * (int)sizeof(float);   // ~152 KB
    cudaFuncSetAttribute(mha_kernel, cudaFuncAttributeMaxDynamicSharedMemorySize, smem_bytes);
    mha_kernel<<<1024/G, THREADS, smem_bytes>>>(x_non, x_seq, mask,
                                                Wq, bq, Wk, bk, Wv, bv, out);
}